// round 10
// baseline (speedup 1.0000x reference)
#include <cuda_runtime.h>

// ---------------------------------------------------------------------------
// GINDeepSigns: N=20000 nodes, K=4 eigs (8 signed copies), E=320000 edges,
// H=64, OUT=16.
// Round 9: revert f32x2 (measured regression), fuse each conv
// (agg + MLP1 + MLP2) into a single kernel via smem staging -> removes
// 164MB/conv of intermediate L2 round-trips and 4 launches total.
// ---------------------------------------------------------------------------

#define NN 20000
#define NEDGE 320000
#define RCOP 8
#define HD 64
#define ROWF (RCOP * HD)      // 512 floats per node
#define R8 (NN * RCOP)        // 160000 rows
#define ZPITCH 68             // padded row pitch in sZ (16B-aligned, bank-safe)

__device__ __align__(16) float g_bufA[R8 * HD];
__device__ __align__(16) float g_bufB[R8 * HD];
__device__ __align__(16) float g_pool[NN * HD];
__device__ int g_rowstart[NN + 1];
__device__ int g_cursor[NN];
__device__ int g_csr[NEDGE];
__device__ int g_bsums[64];
__device__ int g_is64;

__device__ __forceinline__ float4 f4add(float4 a, float4 b) {
    a.x += b.x; a.y += b.y; a.z += b.z; a.w += b.w; return a;
}
__device__ __forceinline__ float4 f4fma(float s, float4 w, float4 a) {
    a.x = fmaf(s, w.x, a.x); a.y = fmaf(s, w.y, a.y);
    a.z = fmaf(s, w.z, a.z); a.w = fmaf(s, w.w, a.w); return a;
}

// Decode edge_index element `pos` for int64 or int32 buffers; clamp to range.
__device__ __forceinline__ int load_idx(const void* ei, int pos) {
    int v;
    if (g_is64) v = (int)((const long long*)ei)[pos];
    else        v = ((const int*)ei)[pos];
    return min(max(v, 0), NN - 1);
}

// ---------------- dtype probe ----------------------------------------------
__global__ void k_detect(const int* __restrict__ ei32) {
    __shared__ int s_any;
    if (threadIdx.x == 0) s_any = 0;
    __syncthreads();
    int any = 0;
    for (int i = threadIdx.x; i < 4096; i += blockDim.x) any |= ei32[2 * i + 1];
    if (any) atomicOr(&s_any, 1);
    __syncthreads();
    if (threadIdx.x == 0) g_is64 = (s_any == 0) ? 1 : 0;
}

// ---------------- CSR build -------------------------------------------------

__global__ void k_zero() {
    int idx = blockIdx.x * blockDim.x + threadIdx.x;
    if (idx <= NN) g_rowstart[idx] = 0;
    if (idx < NN)  g_cursor[idx]   = 0;
}

__global__ void k_count(const void* __restrict__ ei) {
    int e = blockIdx.x * blockDim.x + threadIdx.x;
    if (e >= NEDGE) return;
    int d = load_idx(ei, NEDGE + e);
    atomicAdd(&g_rowstart[d + 1], 1);
}

__global__ void k_scan1() {  // per-512-block inclusive scan
    __shared__ int sh[512];
    int tid = threadIdx.x;
    int idx = blockIdx.x * 512 + tid;
    int v = (idx <= NN) ? g_rowstart[idx] : 0;
    sh[tid] = v; __syncthreads();
    for (int off = 1; off < 512; off <<= 1) {
        int t = (tid >= off) ? sh[tid - off] : 0;
        __syncthreads();
        sh[tid] += t; __syncthreads();
    }
    if (idx <= NN) g_rowstart[idx] = sh[tid];
    if (tid == 511) g_bsums[blockIdx.x] = sh[511];
}

__global__ void k_scan2() {  // exclusive scan of 40 block sums
    __shared__ int sh[64];
    int tid = threadIdx.x;
    int v = (tid < 40) ? g_bsums[tid] : 0;
    sh[tid] = v; __syncthreads();
    for (int off = 1; off < 64; off <<= 1) {
        int t = (tid >= off) ? sh[tid - off] : 0;
        __syncthreads();
        sh[tid] += t; __syncthreads();
    }
    if (tid < 40) g_bsums[tid] = sh[tid] - v;
}

__global__ void k_scan3() {
    int idx = blockIdx.x * blockDim.x + threadIdx.x;
    if (idx <= NN) g_rowstart[idx] += g_bsums[idx >> 9];
}

__global__ void k_scatter(const void* __restrict__ ei) {
    int e = blockIdx.x * blockDim.x + threadIdx.x;
    if (e >= NEDGE) return;
    int s = load_idx(ei, e);
    int d = load_idx(ei, NEDGE + e);
    int pos = atomicAdd(&g_cursor[d], 1);
    int slot = g_rowstart[d] + pos;
    if (slot >= 0 && slot < NEDGE) g_csr[slot] = s;
}

// ---------------- conv0: scalar feature, fused agg + MLP (proven) -----------

__global__ void k_conv0(const float* __restrict__ x,
                        const float* __restrict__ W1, const float* __restrict__ b1,
                        const float* __restrict__ W2, const float* __restrict__ b2,
                        float* __restrict__ out) {
    __shared__ __align__(16) float sW1[64], sb1[64], sW2[64 * 64], sb2[64];
    int tid = threadIdx.x;
    for (int t = tid; t < 64 * 64; t += blockDim.x) sW2[t] = W2[t];
    if (tid < 64) { sW1[tid] = W1[tid]; sb1[tid] = b1[tid]; sb2[tid] = b2[tid]; }
    __syncthreads();

    int idx = blockIdx.x * blockDim.x + tid;
    if (idx >= R8) return;
    int i = idx >> 3, c = idx & 7, k = c & 3;

    float s = x[i * 4 + k];
    int e0 = g_rowstart[i], e1 = g_rowstart[i + 1];
    for (int e = e0; e < e1; e++) s += x[g_csr[e] * 4 + k];
    if (c >= 4) s = -s;   // sign factors out of the linear aggregation

    float4 acc[16];
#pragma unroll
    for (int j = 0; j < 16; j++) acc[j] = ((const float4*)sb2)[j];
#pragma unroll 4
    for (int m = 0; m < 64; m++) {
        float ym = fmaxf(fmaf(s, sW1[m], sb1[m]), 0.0f);
        const float4* w = (const float4*)(sW2 + m * 64);
#pragma unroll
        for (int j = 0; j < 16; j++) acc[j] = f4fma(ym, w[j], acc[j]);
    }
    float4* o = (float4*)(out + (size_t)idx * 64);
#pragma unroll
    for (int j = 0; j < 16; j++) o[j] = acc[j];
}

// ---------------- fused conv: agg + both MLP layers in one kernel -----------
// Block = 256 threads = 8 warps = 8 nodes = 64 rows.
// Phase A: warp-per-node coalesced gather into sZ[64][ZPITCH].
// Phase B: 4 threads/row compute layer1 (relu(z@W1+b1)) into regs.
// Phase C: write y back over sZ; layer2 (y@W2+b2) -> global h'.
__global__ __launch_bounds__(256) void k_conv_fused(
        const float* __restrict__ h,
        const float* __restrict__ W1, const float* __restrict__ b1,
        const float* __restrict__ W2, const float* __restrict__ b2,
        float* __restrict__ out) {
    extern __shared__ __align__(16) float sm[];
    float* sZ  = sm;                 // 64 * ZPITCH = 4352 floats
    float* sW1 = sm + 64 * ZPITCH;   // 4096
    float* sW2 = sW1 + 4096;         // 4096
    float* sb1 = sW2 + 4096;         // 64
    float* sb2 = sb1 + 64;           // 64

    int tid = threadIdx.x;
    for (int t = tid; t < 4096; t += 256) { sW1[t] = W1[t]; sW2[t] = W2[t]; }
    if (tid < 64) { sb1[tid] = b1[tid]; sb2[tid] = b2[tid]; }

    // --- Phase A: gather (z = h_self + sum_neighbors h) ---
    int w = tid >> 5, lane = tid & 31;
    int node = blockIdx.x * 8 + w;
    {
        const float4* self = (const float4*)(h + (size_t)node * ROWF);
        float4 a0 = self[lane], a1 = self[32 + lane],
               a2 = self[64 + lane], a3 = self[96 + lane];
        int e0 = g_rowstart[node], e1 = g_rowstart[node + 1];
        for (int e = e0; e < e1; e++) {
            const float4* src = (const float4*)(h + (size_t)g_csr[e] * ROWF);
            float4 v0 = src[lane], v1 = src[32 + lane],
                   v2 = src[64 + lane], v3 = src[96 + lane];
            a0 = f4add(a0, v0); a1 = f4add(a1, v1);
            a2 = f4add(a2, v2); a3 = f4add(a3, v3);
        }
        // unit u covers floats 4u..4u+3 of the node's 512-float row;
        // local row = w*8 + (u>>4), offset within row = (u&15) float4s.
        int u0 = lane, u1 = 32 + lane, u2 = 64 + lane, u3 = 96 + lane;
        ((float4*)(sZ + (w * 8 + (u0 >> 4)) * ZPITCH))[u0 & 15] = a0;
        ((float4*)(sZ + (w * 8 + (u1 >> 4)) * ZPITCH))[u1 & 15] = a1;
        ((float4*)(sZ + (w * 8 + (u2 >> 4)) * ZPITCH))[u2 & 15] = a2;
        ((float4*)(sZ + (w * 8 + (u3 >> 4)) * ZPITCH))[u3 & 15] = a3;
    }
    __syncthreads();

    // --- Phase B: layer 1, thread (r = tid/4, q = tid%4) computes 16 outputs
    int r = tid >> 2, q = tid & 3;
    float y[16];
    {
        float4 acc[4];
#pragma unroll
        for (int j = 0; j < 4; j++) acc[j] = ((const float4*)(sb1 + q * 16))[j];
        const float* zr = sZ + r * ZPITCH;
#pragma unroll 4
        for (int k = 0; k < 64; k++) {
            float zk = zr[k];
            const float4* wv = (const float4*)(sW1 + k * 64 + q * 16);
#pragma unroll
            for (int j = 0; j < 4; j++) acc[j] = f4fma(zk, wv[j], acc[j]);
        }
#pragma unroll
        for (int j = 0; j < 4; j++) {
            y[4 * j + 0] = fmaxf(acc[j].x, 0.0f);
            y[4 * j + 1] = fmaxf(acc[j].y, 0.0f);
            y[4 * j + 2] = fmaxf(acc[j].z, 0.0f);
            y[4 * j + 3] = fmaxf(acc[j].w, 0.0f);
        }
    }
    __syncthreads();   // all z reads done before overwrite

    // --- Phase C: write y back over sZ, then layer 2 ---
    {
        float4* dst = (float4*)(sZ + r * ZPITCH + q * 16);
        dst[0] = make_float4(y[0],  y[1],  y[2],  y[3]);
        dst[1] = make_float4(y[4],  y[5],  y[6],  y[7]);
        dst[2] = make_float4(y[8],  y[9],  y[10], y[11]);
        dst[3] = make_float4(y[12], y[13], y[14], y[15]);
    }
    __syncthreads();

    float4 acc[4];
#pragma unroll
    for (int j = 0; j < 4; j++) acc[j] = ((const float4*)(sb2 + q * 16))[j];
    const float* yr = sZ + r * ZPITCH;
#pragma unroll 4
    for (int m = 0; m < 64; m++) {
        float ym = yr[m];
        const float4* wv = (const float4*)(sW2 + m * 64 + q * 16);
#pragma unroll
        for (int j = 0; j < 4; j++) acc[j] = f4fma(ym, wv[j], acc[j]);
    }
    float4* o = (float4*)(out + (size_t)(blockIdx.x * 64 + r) * 64 + q * 16);
#pragma unroll
    for (int j = 0; j < 4; j++) o[j] = acc[j];
}

// ---------------- sign-invariant pool: mean over copies ---------------------

__global__ void k_pool(const float* __restrict__ h, float* __restrict__ p) {
    int idx = blockIdx.x * blockDim.x + threadIdx.x;
    if (idx >= NN * 16) return;
    int i = idx >> 4, q = idx & 15;
    const float4* base = (const float4*)(h + (size_t)i * ROWF);
    float4 s = make_float4(0.f, 0.f, 0.f, 0.f);
#pragma unroll
    for (int c = 0; c < 8; c++) s = f4add(s, base[c * 16 + q]);
    s.x *= 0.25f; s.y *= 0.25f; s.z *= 0.25f; s.w *= 0.25f;
    ((float4*)(p + (size_t)i * 64))[q] = s;
}

// ---------------- fused rho: relu(p@W1+b1)@W2+b2, thread per node -----------

__global__ void k_rho(const float* __restrict__ P,
                      const float* __restrict__ W1, const float* __restrict__ b1,
                      const float* __restrict__ W2, const float* __restrict__ b2,
                      float* __restrict__ out) {
    __shared__ __align__(16) float sW1[4096], sW2[1024], sb1[64], sb2[16];
    for (int t = threadIdx.x; t < 4096; t += blockDim.x) sW1[t] = W1[t];
    for (int t = threadIdx.x; t < 1024; t += blockDim.x) sW2[t] = W2[t];
    if (threadIdx.x < 64) sb1[threadIdx.x] = b1[threadIdx.x];
    if (threadIdx.x < 16) sb2[threadIdx.x] = b2[threadIdx.x];
    __syncthreads();

    int n = blockIdx.x * blockDim.x + threadIdx.x;
    if (n >= NN) return;

    float p[64];
    const float4* pr = (const float4*)(P + (size_t)n * 64);
#pragma unroll
    for (int j = 0; j < 16; j++) {
        float4 f = pr[j];
        p[4 * j] = f.x; p[4 * j + 1] = f.y; p[4 * j + 2] = f.z; p[4 * j + 3] = f.w;
    }

    float4 acc[4];
#pragma unroll
    for (int j = 0; j < 4; j++) acc[j] = ((const float4*)sb2)[j];
#pragma unroll 4
    for (int m = 0; m < 64; m++) {
        float d = sb1[m];
#pragma unroll
        for (int k = 0; k < 64; k++) d = fmaf(p[k], sW1[k * 64 + m], d);
        d = fmaxf(d, 0.0f);
        const float4* wv = (const float4*)(sW2 + m * 16);
#pragma unroll
        for (int j = 0; j < 4; j++) acc[j] = f4fma(d, wv[j], acc[j]);
    }
    float4* o = (float4*)(out + (size_t)n * 16);
#pragma unroll
    for (int j = 0; j < 4; j++) o[j] = acc[j];
}

// ---------------------------------------------------------------------------

extern "C" void kernel_launch(void* const* d_in, const int* in_sizes, int n_in,
                              void* d_out, int out_size) {
    const float* x  = (const float*)d_in[0];
    const void*  ei = d_in[1];   // int32 or int64, probed on device
    const float* c0W1 = (const float*)d_in[2];
    const float* c0b1 = (const float*)d_in[3];
    const float* c0W2 = (const float*)d_in[4];
    const float* c0b2 = (const float*)d_in[5];
    const float* c1W1 = (const float*)d_in[6];
    const float* c1b1 = (const float*)d_in[7];
    const float* c1W2 = (const float*)d_in[8];
    const float* c1b2 = (const float*)d_in[9];
    const float* c2W1 = (const float*)d_in[10];
    const float* c2b1 = (const float*)d_in[11];
    const float* c2W2 = (const float*)d_in[12];
    const float* c2b2 = (const float*)d_in[13];
    const float* rW1  = (const float*)d_in[14];
    const float* rb1  = (const float*)d_in[15];
    const float* rW2  = (const float*)d_in[16];
    const float* rb2  = (const float*)d_in[17];
    float* out = (float*)d_out;

    float *A, *B, *P;
    cudaGetSymbolAddress((void**)&A, g_bufA);
    cudaGetSymbolAddress((void**)&B, g_bufB);
    cudaGetSymbolAddress((void**)&P, g_pool);

    const int FUSED_SMEM = (64 * ZPITCH + 4096 + 4096 + 64 + 64) * 4;  // 50688 B
    cudaFuncSetAttribute(k_conv_fused,
                         cudaFuncAttributeMaxDynamicSharedMemorySize, FUSED_SMEM);

    // dtype probe + CSR build (per launch; graph-capturable, deterministic)
    k_detect<<<1, 256>>>((const int*)ei);
    k_zero<<<(NN + 256) / 256, 256>>>();
    k_count<<<NEDGE / 256, 256>>>(ei);
    k_scan1<<<40, 512>>>();
    k_scan2<<<1, 64>>>();
    k_scan3<<<(NN + 256) / 256, 256>>>();
    k_scatter<<<NEDGE / 256, 256>>>(ei);

    // conv0 (scalar in-feature, fused)
    k_conv0<<<R8 / 256, 256>>>(x, c0W1, c0b1, c0W2, c0b2, A);

    // conv1 + conv2: single fused kernel each (agg + MLP1 + MLP2)
    k_conv_fused<<<NN / 8, 256, FUSED_SMEM>>>(A, c1W1, c1b1, c1W2, c1b2, B);
    k_conv_fused<<<NN / 8, 256, FUSED_SMEM>>>(B, c2W1, c2b1, c2W2, c2b2, A);

    // pool + fused rho
    k_pool<<<(NN * 16) / 256, 256>>>(A, P);
    k_rho<<<(NN + 255) / 256, 256>>>(P, rW1, rb1, rW2, rb2, out);
}

// round 11
// speedup vs baseline: 1.6865x; 1.6865x over previous
#include <cuda_runtime.h>

// ---------------------------------------------------------------------------
// GINDeepSigns: N=20000 nodes, K=4 eigs (8 signed copies), E=320000 edges,
// H=64, OUT=16.
// Round 10: revert round-9 conv fusion (measured LDS-conflict regression).
// Back to proven 501us structure, plus two conservative fusions that keep
// the warp-broadcast weight-LDS pattern intact:
//   - k_mlp2: both conv MLP layers in one kernel, y held in registers
//     (drops 164MB of intermediate L2 round-trips + 2 launches)
//   - k_rho: pool fused into rho (drops 10MB + 1 launch)
// ---------------------------------------------------------------------------

#define NN 20000
#define NEDGE 320000
#define RCOP 8
#define HD 64
#define ROWF (RCOP * HD)      // 512 floats per node
#define R8 (NN * RCOP)        // 160000 rows

__device__ __align__(16) float g_bufA[R8 * HD];
__device__ __align__(16) float g_bufB[R8 * HD];
__device__ int g_rowstart[NN + 1];
__device__ int g_cursor[NN];
__device__ int g_csr[NEDGE];
__device__ int g_bsums[64];
__device__ int g_is64;

__device__ __forceinline__ float4 f4add(float4 a, float4 b) {
    a.x += b.x; a.y += b.y; a.z += b.z; a.w += b.w; return a;
}
__device__ __forceinline__ float4 f4fma(float s, float4 w, float4 a) {
    a.x = fmaf(s, w.x, a.x); a.y = fmaf(s, w.y, a.y);
    a.z = fmaf(s, w.z, a.z); a.w = fmaf(s, w.w, a.w); return a;
}

// Decode edge_index element `pos` for int64 or int32 buffers; clamp to range.
__device__ __forceinline__ int load_idx(const void* ei, int pos) {
    int v;
    if (g_is64) v = (int)((const long long*)ei)[pos];
    else        v = ((const int*)ei)[pos];
    return min(max(v, 0), NN - 1);
}

// ---------------- dtype probe ----------------------------------------------
__global__ void k_detect(const int* __restrict__ ei32) {
    __shared__ int s_any;
    if (threadIdx.x == 0) s_any = 0;
    __syncthreads();
    int any = 0;
    for (int i = threadIdx.x; i < 4096; i += blockDim.x) any |= ei32[2 * i + 1];
    if (any) atomicOr(&s_any, 1);
    __syncthreads();
    if (threadIdx.x == 0) g_is64 = (s_any == 0) ? 1 : 0;
}

// ---------------- CSR build -------------------------------------------------

__global__ void k_zero() {
    int idx = blockIdx.x * blockDim.x + threadIdx.x;
    if (idx <= NN) g_rowstart[idx] = 0;
    if (idx < NN)  g_cursor[idx]   = 0;
}

__global__ void k_count(const void* __restrict__ ei) {
    int e = blockIdx.x * blockDim.x + threadIdx.x;
    if (e >= NEDGE) return;
    int d = load_idx(ei, NEDGE + e);
    atomicAdd(&g_rowstart[d + 1], 1);
}

__global__ void k_scan1() {  // per-512-block inclusive scan
    __shared__ int sh[512];
    int tid = threadIdx.x;
    int idx = blockIdx.x * 512 + tid;
    int v = (idx <= NN) ? g_rowstart[idx] : 0;
    sh[tid] = v; __syncthreads();
    for (int off = 1; off < 512; off <<= 1) {
        int t = (tid >= off) ? sh[tid - off] : 0;
        __syncthreads();
        sh[tid] += t; __syncthreads();
    }
    if (idx <= NN) g_rowstart[idx] = sh[tid];
    if (tid == 511) g_bsums[blockIdx.x] = sh[511];
}

__global__ void k_scan2() {  // exclusive scan of 40 block sums
    __shared__ int sh[64];
    int tid = threadIdx.x;
    int v = (tid < 40) ? g_bsums[tid] : 0;
    sh[tid] = v; __syncthreads();
    for (int off = 1; off < 64; off <<= 1) {
        int t = (tid >= off) ? sh[tid - off] : 0;
        __syncthreads();
        sh[tid] += t; __syncthreads();
    }
    if (tid < 40) g_bsums[tid] = sh[tid] - v;
}

__global__ void k_scan3() {
    int idx = blockIdx.x * blockDim.x + threadIdx.x;
    if (idx <= NN) g_rowstart[idx] += g_bsums[idx >> 9];
}

__global__ void k_scatter(const void* __restrict__ ei) {
    int e = blockIdx.x * blockDim.x + threadIdx.x;
    if (e >= NEDGE) return;
    int s = load_idx(ei, e);
    int d = load_idx(ei, NEDGE + e);
    int pos = atomicAdd(&g_cursor[d], 1);
    int slot = g_rowstart[d] + pos;
    if (slot >= 0 && slot < NEDGE) g_csr[slot] = s;
}

// ---------------- conv0: scalar feature, fused agg + MLP (proven) -----------

__global__ void k_conv0(const float* __restrict__ x,
                        const float* __restrict__ W1, const float* __restrict__ b1,
                        const float* __restrict__ W2, const float* __restrict__ b2,
                        float* __restrict__ out) {
    __shared__ __align__(16) float sW1[64], sb1[64], sW2[64 * 64], sb2[64];
    int tid = threadIdx.x;
    for (int t = tid; t < 64 * 64; t += blockDim.x) sW2[t] = W2[t];
    if (tid < 64) { sW1[tid] = W1[tid]; sb1[tid] = b1[tid]; sb2[tid] = b2[tid]; }
    __syncthreads();

    int idx = blockIdx.x * blockDim.x + tid;
    if (idx >= R8) return;
    int i = idx >> 3, c = idx & 7, k = c & 3;

    float s = x[i * 4 + k];
    int e0 = g_rowstart[i], e1 = g_rowstart[i + 1];
    for (int e = e0; e < e1; e++) s += x[g_csr[e] * 4 + k];
    if (c >= 4) s = -s;   // sign factors out of the linear aggregation

    float4 acc[16];
#pragma unroll
    for (int j = 0; j < 16; j++) acc[j] = ((const float4*)sb2)[j];
#pragma unroll 4
    for (int m = 0; m < 64; m++) {
        float ym = fmaxf(fmaf(s, sW1[m], sb1[m]), 0.0f);
        const float4* w = (const float4*)(sW2 + m * 64);
#pragma unroll
        for (int j = 0; j < 16; j++) acc[j] = f4fma(ym, w[j], acc[j]);
    }
    float4* o = (float4*)(out + (size_t)idx * 64);
#pragma unroll
    for (int j = 0; j < 16; j++) o[j] = acc[j];
}

// ---------------- aggregation: warp per node, coalesced 2KB row gather ------

__global__ void k_agg(const float* __restrict__ h, float* __restrict__ z) {
    int gw   = (blockIdx.x * blockDim.x + threadIdx.x) >> 5;
    int lane = threadIdx.x & 31;
    if (gw >= NN) return;
    const float4* self = (const float4*)(h + (size_t)gw * ROWF);
    float4 a0 = self[lane], a1 = self[32 + lane], a2 = self[64 + lane], a3 = self[96 + lane];
    int e0 = g_rowstart[gw], e1 = g_rowstart[gw + 1];
    for (int e = e0; e < e1; e++) {
        const float4* src = (const float4*)(h + (size_t)g_csr[e] * ROWF);
        float4 v0 = src[lane], v1 = src[32 + lane], v2 = src[64 + lane], v3 = src[96 + lane];
        a0 = f4add(a0, v0); a1 = f4add(a1, v1); a2 = f4add(a2, v2); a3 = f4add(a3, v3);
    }
    float4* zo = (float4*)(z + (size_t)gw * ROWF);
    zo[lane] = a0; zo[32 + lane] = a1; zo[64 + lane] = a2; zo[96 + lane] = a3;
}

// ---------------- fused 2-layer MLP: thread per row, y in registers ---------
// Same broadcast-weight LDS pattern as the proven k_mlp, run twice back to
// back with the intermediate held in registers (no global y round-trip).

__global__ __launch_bounds__(128) void k_mlp2(
        const float* __restrict__ in,
        const float* __restrict__ W1, const float* __restrict__ b1,
        const float* __restrict__ W2, const float* __restrict__ b2,
        float* __restrict__ out) {
    __shared__ __align__(16) float sW1[4096], sW2[4096], sb1[64], sb2[64];
    for (int t = threadIdx.x; t < 4096; t += 128) { sW1[t] = W1[t]; sW2[t] = W2[t]; }
    if (threadIdx.x < 64) { sb1[threadIdx.x] = b1[threadIdx.x]; sb2[threadIdx.x] = b2[threadIdx.x]; }
    __syncthreads();

    int row = blockIdx.x * 128 + threadIdx.x;   // grid sized exactly R8/128

    // ---- layer 1: acc = relu(z @ W1 + b1), z streamed from global ----
    float4 a[16];
#pragma unroll
    for (int j = 0; j < 16; j++) a[j] = ((const float4*)sb1)[j];

    const float4* ir = (const float4*)(in + (size_t)row * 64);
#pragma unroll 4
    for (int kk = 0; kk < 16; kk++) {
        float4 f = ir[kk];
        float zs[4] = {f.x, f.y, f.z, f.w};
#pragma unroll
        for (int u = 0; u < 4; u++) {
            float zk = zs[u];
            const float4* w = (const float4*)(sW1 + (kk * 4 + u) * 64);
#pragma unroll
            for (int j = 0; j < 16; j++) a[j] = f4fma(zk, w[j], a[j]);
        }
    }
#pragma unroll
    for (int j = 0; j < 16; j++) {
        a[j].x = fmaxf(a[j].x, 0.0f); a[j].y = fmaxf(a[j].y, 0.0f);
        a[j].z = fmaxf(a[j].z, 0.0f); a[j].w = fmaxf(a[j].w, 0.0f);
    }

    // ---- layer 2: c = y @ W2 + b2, y taken from registers ----
    float4 c[16];
#pragma unroll
    for (int j = 0; j < 16; j++) c[j] = ((const float4*)sb2)[j];

#pragma unroll 4
    for (int g = 0; g < 16; g++) {
        float4 yv = a[g];
        float ys[4] = {yv.x, yv.y, yv.z, yv.w};
#pragma unroll
        for (int u = 0; u < 4; u++) {
            float ym = ys[u];
            const float4* w = (const float4*)(sW2 + (g * 4 + u) * 64);
#pragma unroll
            for (int j = 0; j < 16; j++) c[j] = f4fma(ym, w[j], c[j]);
        }
    }

    float4* o = (float4*)(out + (size_t)row * 64);
#pragma unroll
    for (int j = 0; j < 16; j++) o[j] = c[j];
}

// ---------------- fused pool + rho: thread per node -------------------------
// p = 0.25 * sum_c h[i,c,:]; out = relu(p@W1+b1)@W2+b2

__global__ void k_rho(const float* __restrict__ h,
                      const float* __restrict__ W1, const float* __restrict__ b1,
                      const float* __restrict__ W2, const float* __restrict__ b2,
                      float* __restrict__ out) {
    __shared__ __align__(16) float sW1[4096], sW2[1024], sb1[64], sb2[16];
    for (int t = threadIdx.x; t < 4096; t += blockDim.x) sW1[t] = W1[t];
    for (int t = threadIdx.x; t < 1024; t += blockDim.x) sW2[t] = W2[t];
    if (threadIdx.x < 64) sb1[threadIdx.x] = b1[threadIdx.x];
    if (threadIdx.x < 16) sb2[threadIdx.x] = b2[threadIdx.x];
    __syncthreads();

    int n = blockIdx.x * blockDim.x + threadIdx.x;
    if (n >= NN) return;

    // pool: mean over 8 signed copies (x0.25 = /4 eigenvectors)
    float p[64];
    {
        const float4* base = (const float4*)(h + (size_t)n * ROWF);
#pragma unroll
        for (int j = 0; j < 16; j++) {
            float4 s = base[j];
#pragma unroll
            for (int cc = 1; cc < 8; cc++) s = f4add(s, base[cc * 16 + j]);
            p[4 * j + 0] = s.x * 0.25f; p[4 * j + 1] = s.y * 0.25f;
            p[4 * j + 2] = s.z * 0.25f; p[4 * j + 3] = s.w * 0.25f;
        }
    }

    float4 acc[4];
#pragma unroll
    for (int j = 0; j < 4; j++) acc[j] = ((const float4*)sb2)[j];
#pragma unroll 4
    for (int m = 0; m < 64; m++) {
        float d = sb1[m];
#pragma unroll
        for (int k = 0; k < 64; k++) d = fmaf(p[k], sW1[k * 64 + m], d);
        d = fmaxf(d, 0.0f);
        const float4* wv = (const float4*)(sW2 + m * 16);
#pragma unroll
        for (int j = 0; j < 4; j++) acc[j] = f4fma(d, wv[j], acc[j]);
    }
    float4* o = (float4*)(out + (size_t)n * 16);
#pragma unroll
    for (int j = 0; j < 4; j++) o[j] = acc[j];
}

// ---------------------------------------------------------------------------

extern "C" void kernel_launch(void* const* d_in, const int* in_sizes, int n_in,
                              void* d_out, int out_size) {
    const float* x  = (const float*)d_in[0];
    const void*  ei = d_in[1];   // int32 or int64, probed on device
    const float* c0W1 = (const float*)d_in[2];
    const float* c0b1 = (const float*)d_in[3];
    const float* c0W2 = (const float*)d_in[4];
    const float* c0b2 = (const float*)d_in[5];
    const float* c1W1 = (const float*)d_in[6];
    const float* c1b1 = (const float*)d_in[7];
    const float* c1W2 = (const float*)d_in[8];
    const float* c1b2 = (const float*)d_in[9];
    const float* c2W1 = (const float*)d_in[10];
    const float* c2b1 = (const float*)d_in[11];
    const float* c2W2 = (const float*)d_in[12];
    const float* c2b2 = (const float*)d_in[13];
    const float* rW1  = (const float*)d_in[14];
    const float* rb1  = (const float*)d_in[15];
    const float* rW2  = (const float*)d_in[16];
    const float* rb2  = (const float*)d_in[17];
    float* out = (float*)d_out;

    float *A, *B;
    cudaGetSymbolAddress((void**)&A, g_bufA);
    cudaGetSymbolAddress((void**)&B, g_bufB);

    // dtype probe + CSR build (per launch; graph-capturable, deterministic)
    k_detect<<<1, 256>>>((const int*)ei);
    k_zero<<<(NN + 256) / 256, 256>>>();
    k_count<<<NEDGE / 256, 256>>>(ei);
    k_scan1<<<40, 512>>>();
    k_scan2<<<1, 64>>>();
    k_scan3<<<(NN + 256) / 256, 256>>>();
    k_scatter<<<NEDGE / 256, 256>>>(ei);

    // conv0 (scalar in-feature, fused)
    k_conv0<<<R8 / 256, 256>>>(x, c0W1, c0b1, c0W2, c0b2, A);

    // conv1: agg + fused 2-layer MLP (y stays in registers)
    k_agg<<<NN / 8, 256>>>(A, B);
    k_mlp2<<<R8 / 128, 128>>>(B, c1W1, c1b1, c1W2, c1b2, A);

    // conv2
    k_agg<<<NN / 8, 256>>>(A, B);
    k_mlp2<<<R8 / 128, 128>>>(B, c2W1, c2b1, c2W2, c2b2, A);

    // fused pool + rho
    k_rho<<<(NN + 255) / 256, 256>>>(A, rW1, rb1, rW2, rb2, out);
}

// round 12
// speedup vs baseline: 2.3382x; 1.3864x over previous
#include <cuda_runtime.h>

// ---------------------------------------------------------------------------
// GINDeepSigns: N=20000 nodes, K=4 eigs (8 signed copies), E=320000 edges,
// H=64, OUT=16.
// Round 11: algebraic folding. Everything between ReLUs is linear, so
//   M2_l -> (I+A) -> M1_{l+1}  collapses to  (agg y)@(W2*W1') + (1+deg)v + b1'
// and M2_2 folds through the pool into rho. Big 64x64 GEMV passes over
// 160000 rows drop from 5 to 2. Weight products precomputed per launch.
// ---------------------------------------------------------------------------

#define NN 20000
#define NEDGE 320000
#define RCOP 8
#define HD 64
#define ROWF (RCOP * HD)      // 512 floats per node
#define R8 (NN * RCOP)        // 160000 rows

__device__ __align__(16) float g_bufA[R8 * HD];
__device__ __align__(16) float g_bufB[R8 * HD];
__device__ int g_rowstart[NN + 1];
__device__ int g_cursor[NN];
__device__ int g_csr[NEDGE];
__device__ int g_bsums[64];
__device__ int g_is64;
// folded weights (computed per launch by k_prep)
__device__ __align__(16) float g_P1[4096];  // c0W2 @ c1W1
__device__ __align__(16) float g_v1[64];    // c0b2 @ c1W1
__device__ __align__(16) float g_P2[4096];  // c1W2 @ c2W1
__device__ __align__(16) float g_v2[64];    // c1b2 @ c2W1
__device__ __align__(16) float g_Pr[4096];  // c2W2 @ rW1
__device__ __align__(16) float g_br[64];    // 2*(c2b2 @ rW1) + rb1

__device__ __forceinline__ float4 f4add(float4 a, float4 b) {
    a.x += b.x; a.y += b.y; a.z += b.z; a.w += b.w; return a;
}
__device__ __forceinline__ float4 f4fma(float s, float4 w, float4 a) {
    a.x = fmaf(s, w.x, a.x); a.y = fmaf(s, w.y, a.y);
    a.z = fmaf(s, w.z, a.z); a.w = fmaf(s, w.w, a.w); return a;
}

// Decode edge_index element `pos` for int64 or int32 buffers; clamp to range.
__device__ __forceinline__ int load_idx(const void* ei, int pos) {
    int v;
    if (g_is64) v = (int)((const long long*)ei)[pos];
    else        v = ((const int*)ei)[pos];
    return min(max(v, 0), NN - 1);
}

// ---------------- dtype probe ----------------------------------------------
__global__ void k_detect(const int* __restrict__ ei32) {
    __shared__ int s_any;
    if (threadIdx.x == 0) s_any = 0;
    __syncthreads();
    int any = 0;
    for (int i = threadIdx.x; i < 4096; i += blockDim.x) any |= ei32[2 * i + 1];
    if (any) atomicOr(&s_any, 1);
    __syncthreads();
    if (threadIdx.x == 0) g_is64 = (s_any == 0) ? 1 : 0;
}

// ---------------- CSR build -------------------------------------------------

__global__ void k_zero() {
    int idx = blockIdx.x * blockDim.x + threadIdx.x;
    if (idx <= NN) g_rowstart[idx] = 0;
    if (idx < NN)  g_cursor[idx]   = 0;
}

__global__ void k_count(const void* __restrict__ ei) {
    int e = blockIdx.x * blockDim.x + threadIdx.x;
    if (e >= NEDGE) return;
    int d = load_idx(ei, NEDGE + e);
    atomicAdd(&g_rowstart[d + 1], 1);
}

__global__ void k_scan1() {  // per-512-block inclusive scan
    __shared__ int sh[512];
    int tid = threadIdx.x;
    int idx = blockIdx.x * 512 + tid;
    int v = (idx <= NN) ? g_rowstart[idx] : 0;
    sh[tid] = v; __syncthreads();
    for (int off = 1; off < 512; off <<= 1) {
        int t = (tid >= off) ? sh[tid - off] : 0;
        __syncthreads();
        sh[tid] += t; __syncthreads();
    }
    if (idx <= NN) g_rowstart[idx] = sh[tid];
    if (tid == 511) g_bsums[blockIdx.x] = sh[511];
}

__global__ void k_scan2() {  // exclusive scan of 40 block sums
    __shared__ int sh[64];
    int tid = threadIdx.x;
    int v = (tid < 40) ? g_bsums[tid] : 0;
    sh[tid] = v; __syncthreads();
    for (int off = 1; off < 64; off <<= 1) {
        int t = (tid >= off) ? sh[tid - off] : 0;
        __syncthreads();
        sh[tid] += t; __syncthreads();
    }
    if (tid < 40) g_bsums[tid] = sh[tid] - v;
}

__global__ void k_scan3() {
    int idx = blockIdx.x * blockDim.x + threadIdx.x;
    if (idx <= NN) g_rowstart[idx] += g_bsums[idx >> 9];
}

__global__ void k_scatter(const void* __restrict__ ei) {
    int e = blockIdx.x * blockDim.x + threadIdx.x;
    if (e >= NEDGE) return;
    int s = load_idx(ei, e);
    int d = load_idx(ei, NEDGE + e);
    int pos = atomicAdd(&g_cursor[d], 1);
    int slot = g_rowstart[d] + pos;
    if (slot >= 0 && slot < NEDGE) g_csr[slot] = s;
}

// ---------------- weight-product prep: 3 blocks, one product each -----------

__global__ void k_prep(const float* __restrict__ c0W2, const float* __restrict__ c0b2,
                       const float* __restrict__ c1W1,
                       const float* __restrict__ c1W2, const float* __restrict__ c1b2,
                       const float* __restrict__ c2W1,
                       const float* __restrict__ c2W2, const float* __restrict__ c2b2,
                       const float* __restrict__ rW1,  const float* __restrict__ rb1) {
    __shared__ __align__(16) float sA[4096], sB[4096], sb2[64];
    const float *W2, *b2, *W1, *addb; float scale; float *P, *v;
    if (blockIdx.x == 0)      { W2 = c0W2; b2 = c0b2; W1 = c1W1; scale = 1.f; addb = 0;   P = g_P1; v = g_v1; }
    else if (blockIdx.x == 1) { W2 = c1W2; b2 = c1b2; W1 = c2W1; scale = 1.f; addb = 0;   P = g_P2; v = g_v2; }
    else                      { W2 = c2W2; b2 = c2b2; W1 = rW1;  scale = 2.f; addb = rb1; P = g_Pr; v = g_br; }

    int tid = threadIdx.x;
    for (int t = tid; t < 4096; t += 256) { sA[t] = W2[t]; sB[t] = W1[t]; }
    if (tid < 64) sb2[tid] = b2[tid];
    __syncthreads();

    for (int t = tid; t < 4096; t += 256) {
        int a = t >> 6, c = t & 63;
        float s = 0.f;
#pragma unroll 8
        for (int b = 0; b < 64; b++) s = fmaf(sA[a * 64 + b], sB[b * 64 + c], s);
        P[t] = s;
    }
    if (tid < 64) {
        float s = 0.f;
#pragma unroll 8
        for (int b = 0; b < 64; b++) s = fmaf(sb2[b], sB[b * 64 + tid], s);
        v[tid] = scale * s + (addb ? addb[tid] : 0.f);
    }
}

// ---------------- conv0 (folded): y0 = relu(s * W1_0 + b1_0) ----------------

__global__ void k_conv0y(const float* __restrict__ x,
                         const float* __restrict__ W1, const float* __restrict__ b1,
                         float* __restrict__ out) {
    __shared__ __align__(16) float sW1[64], sb1[64];
    int tid = threadIdx.x;
    if (tid < 64) { sW1[tid] = W1[tid]; sb1[tid] = b1[tid]; }
    __syncthreads();

    int idx = blockIdx.x * blockDim.x + tid;
    if (idx >= R8) return;
    int i = idx >> 3, c = idx & 7, k = c & 3;

    float s = x[i * 4 + k];
    int e0 = g_rowstart[i], e1 = g_rowstart[i + 1];
    for (int e = e0; e < e1; e++) s += x[g_csr[e] * 4 + k];
    if (c >= 4) s = -s;   // sign factors out of the linear aggregation

    float4* o = (float4*)(out + (size_t)idx * 64);
#pragma unroll
    for (int j = 0; j < 16; j++) {
        float4 w = ((const float4*)sW1)[j];
        float4 bb = ((const float4*)sb1)[j];
        float4 r;
        r.x = fmaxf(fmaf(s, w.x, bb.x), 0.0f);
        r.y = fmaxf(fmaf(s, w.y, bb.y), 0.0f);
        r.z = fmaxf(fmaf(s, w.z, bb.z), 0.0f);
        r.w = fmaxf(fmaf(s, w.w, bb.w), 0.0f);
        o[j] = r;
    }
}

// ---------------- aggregation: warp per node, coalesced 2KB row gather ------

__global__ void k_agg(const float* __restrict__ h, float* __restrict__ z) {
    int gw   = (blockIdx.x * blockDim.x + threadIdx.x) >> 5;
    int lane = threadIdx.x & 31;
    if (gw >= NN) return;
    const float4* self = (const float4*)(h + (size_t)gw * ROWF);
    float4 a0 = self[lane], a1 = self[32 + lane], a2 = self[64 + lane], a3 = self[96 + lane];
    int e0 = g_rowstart[gw], e1 = g_rowstart[gw + 1];
    for (int e = e0; e < e1; e++) {
        const float4* src = (const float4*)(h + (size_t)g_csr[e] * ROWF);
        float4 v0 = src[lane], v1 = src[32 + lane], v2 = src[64 + lane], v3 = src[96 + lane];
        a0 = f4add(a0, v0); a1 = f4add(a1, v1); a2 = f4add(a2, v2); a3 = f4add(a3, v3);
    }
    float4* zo = (float4*)(z + (size_t)gw * ROWF);
    zo[lane] = a0; zo[32 + lane] = a1; zo[64 + lane] = a2; zo[96 + lane] = a3;
}

// ---------------- folded conv layer: y' = relu(g @ P + (1+deg)v + b1) -------
// Thread per row, broadcast-weight LDS pattern (proven).

__global__ __launch_bounds__(128) void k_lin(
        const float* __restrict__ in,       // agg output g, [R8,64]
        const float* __restrict__ P,        // folded 64x64 product
        const float* __restrict__ v,        // b2_prev @ W1_cur
        const float* __restrict__ b1,       // current layer-1 bias
        float* __restrict__ out) {
    __shared__ __align__(16) float sP[4096], sv[64], sb[64];
    for (int t = threadIdx.x; t < 4096; t += 128) sP[t] = P[t];
    if (threadIdx.x < 64) { sv[threadIdx.x] = v[threadIdx.x]; sb[threadIdx.x] = b1[threadIdx.x]; }
    __syncthreads();

    int row = blockIdx.x * 128 + threadIdx.x;   // grid = R8/128 exactly
    int node = row >> 3;
    float degp1 = (float)(g_rowstart[node + 1] - g_rowstart[node] + 1);

    float4 a[16];
#pragma unroll
    for (int j = 0; j < 16; j++)
        a[j] = f4fma(degp1, ((const float4*)sv)[j], ((const float4*)sb)[j]);

    const float4* ir = (const float4*)(in + (size_t)row * 64);
#pragma unroll 4
    for (int kk = 0; kk < 16; kk++) {
        float4 f = ir[kk];
        float zs[4] = {f.x, f.y, f.z, f.w};
#pragma unroll
        for (int u = 0; u < 4; u++) {
            float zk = zs[u];
            const float4* w = (const float4*)(sP + (kk * 4 + u) * 64);
#pragma unroll
            for (int j = 0; j < 16; j++) a[j] = f4fma(zk, w[j], a[j]);
        }
    }
    float4* o = (float4*)(out + (size_t)row * 64);
#pragma unroll
    for (int j = 0; j < 16; j++) {
        float4 r = a[j];
        r.x = fmaxf(r.x, 0.0f); r.y = fmaxf(r.y, 0.0f);
        r.z = fmaxf(r.z, 0.0f); r.w = fmaxf(r.w, 0.0f);
        o[j] = r;
    }
}

// ---------------- folded pool + rho: thread per node ------------------------
// m = 0.25*sum_c y2[i,c,:]; out = relu(m@Pr + br) @ rW2 + rb2

__global__ void k_rho(const float* __restrict__ y2,
                      const float* __restrict__ W2, const float* __restrict__ b2,
                      float* __restrict__ out) {
    __shared__ __align__(16) float sW1[4096], sW2[1024], sb1[64], sb2[16];
    for (int t = threadIdx.x; t < 4096; t += blockDim.x) sW1[t] = g_Pr[t];
    for (int t = threadIdx.x; t < 1024; t += blockDim.x) sW2[t] = W2[t];
    if (threadIdx.x < 64) sb1[threadIdx.x] = g_br[threadIdx.x];
    if (threadIdx.x < 16) sb2[threadIdx.x] = b2[threadIdx.x];
    __syncthreads();

    int n = blockIdx.x * blockDim.x + threadIdx.x;
    if (n >= NN) return;

    float p[64];
    {
        const float4* base = (const float4*)(y2 + (size_t)n * ROWF);
#pragma unroll
        for (int j = 0; j < 16; j++) {
            float4 s = base[j];
#pragma unroll
            for (int cc = 1; cc < 8; cc++) s = f4add(s, base[cc * 16 + j]);
            p[4 * j + 0] = s.x * 0.25f; p[4 * j + 1] = s.y * 0.25f;
            p[4 * j + 2] = s.z * 0.25f; p[4 * j + 3] = s.w * 0.25f;
        }
    }

    float4 acc[4];
#pragma unroll
    for (int j = 0; j < 4; j++) acc[j] = ((const float4*)sb2)[j];
#pragma unroll 4
    for (int m = 0; m < 64; m++) {
        float d = sb1[m];
#pragma unroll
        for (int k = 0; k < 64; k++) d = fmaf(p[k], sW1[k * 64 + m], d);
        d = fmaxf(d, 0.0f);
        const float4* wv = (const float4*)(sW2 + m * 16);
#pragma unroll
        for (int j = 0; j < 4; j++) acc[j] = f4fma(d, wv[j], acc[j]);
    }
    float4* o = (float4*)(out + (size_t)n * 16);
#pragma unroll
    for (int j = 0; j < 4; j++) o[j] = acc[j];
}

// ---------------------------------------------------------------------------

extern "C" void kernel_launch(void* const* d_in, const int* in_sizes, int n_in,
                              void* d_out, int out_size) {
    const float* x  = (const float*)d_in[0];
    const void*  ei = d_in[1];   // int32 or int64, probed on device
    const float* c0W1 = (const float*)d_in[2];
    const float* c0b1 = (const float*)d_in[3];
    const float* c0W2 = (const float*)d_in[4];
    const float* c0b2 = (const float*)d_in[5];
    const float* c1W1 = (const float*)d_in[6];
    const float* c1b1 = (const float*)d_in[7];
    const float* c1W2 = (const float*)d_in[8];
    const float* c1b2 = (const float*)d_in[9];
    const float* c2W1 = (const float*)d_in[10];
    const float* c2b1 = (const float*)d_in[11];
    const float* c2W2 = (const float*)d_in[12];
    const float* c2b2 = (const float*)d_in[13];
    const float* rW1  = (const float*)d_in[14];
    const float* rb1  = (const float*)d_in[15];
    const float* rW2  = (const float*)d_in[16];
    const float* rb2  = (const float*)d_in[17];
    float* out = (float*)d_out;

    float *A, *B, *P1, *V1, *P2, *V2;
    cudaGetSymbolAddress((void**)&A,  g_bufA);
    cudaGetSymbolAddress((void**)&B,  g_bufB);
    cudaGetSymbolAddress((void**)&P1, g_P1);
    cudaGetSymbolAddress((void**)&V1, g_v1);
    cudaGetSymbolAddress((void**)&P2, g_P2);
    cudaGetSymbolAddress((void**)&V2, g_v2);

    // dtype probe + CSR build + weight folding (per launch; capturable)
    k_detect<<<1, 256>>>((const int*)ei);
    k_zero<<<(NN + 256) / 256, 256>>>();
    k_count<<<NEDGE / 256, 256>>>(ei);
    k_scan1<<<40, 512>>>();
    k_scan2<<<1, 64>>>();
    k_scan3<<<(NN + 256) / 256, 256>>>();
    k_scatter<<<NEDGE / 256, 256>>>(ei);
    k_prep<<<3, 256>>>(c0W2, c0b2, c1W1, c1W2, c1b2, c2W1, c2W2, c2b2, rW1, rb1);

    // conv0 folded: y0 only
    k_conv0y<<<R8 / 256, 256>>>(x, c0W1, c0b1, A);

    // boundary 0->1: agg y0, folded GEMV -> y1
    k_agg<<<NN / 8, 256>>>(A, B);
    k_lin<<<R8 / 128, 128>>>(B, P1, V1, c1b1, A);

    // boundary 1->2: agg y1, folded GEMV -> y2
    k_agg<<<NN / 8, 256>>>(A, B);
    k_lin<<<R8 / 128, 128>>>(B, P2, V2, c2b1, A);

    // folded pool + rho (W2_2 folded through pool into rho layer 1)
    k_rho<<<(NN + 255) / 256, 256>>>(A, rW2, rb2, out);
}

// round 17
// speedup vs baseline: 2.4244x; 1.0369x over previous
#include <cuda_runtime.h>

// ---------------------------------------------------------------------------
// GINDeepSigns: N=20000 nodes, K=4 eigs (8 signed copies), E=320000 edges,
// H=64, OUT=16.
// Round 16 (resubmit of round-15 fix after infra failure): s-space boundary
// 0->1 with CORRECT conv0 semantics. conv0 aggregates BEFORE its MLP, so
// y0_j = MLP0(sgn*S_j) with S_j = x_j + sum_{u->j} x_u (aggregated scalar).
// k_sagg precomputes S (N x 4, ~3us); k_b01 then recomputes
// relu(sgn*S_j*W1+b1) per edge in registers and applies the folded P1 GEMV
// in the same kernel. Replaces conv0y + agg#1 + lin#1.
// ---------------------------------------------------------------------------

#define NN 20000
#define NEDGE 320000
#define RCOP 8
#define HD 64
#define ROWF (RCOP * HD)      // 512 floats per node
#define R8 (NN * RCOP)        // 160000 rows

__device__ __align__(16) float g_bufA[R8 * HD];
__device__ __align__(16) float g_bufB[R8 * HD];
__device__ __align__(16) float g_sx[NN * 4];   // aggregated scalars S[i][k]
__device__ int g_rowstart[NN + 1];
__device__ int g_cursor[NN];
__device__ int g_csr[NEDGE];
__device__ int g_bsums[64];
__device__ int g_is64;
// folded weights (computed per launch by k_prep)
__device__ __align__(16) float g_P1[4096];  // c0W2 @ c1W1
__device__ __align__(16) float g_v1[64];    // c0b2 @ c1W1
__device__ __align__(16) float g_P2[4096];  // c1W2 @ c2W1
__device__ __align__(16) float g_v2[64];    // c1b2 @ c2W1
__device__ __align__(16) float g_Pr[4096];  // c2W2 @ rW1
__device__ __align__(16) float g_br[64];    // 2*(c2b2 @ rW1) + rb1

__device__ __forceinline__ float4 f4add(float4 a, float4 b) {
    a.x += b.x; a.y += b.y; a.z += b.z; a.w += b.w; return a;
}
__device__ __forceinline__ float4 f4fma(float s, float4 w, float4 a) {
    a.x = fmaf(s, w.x, a.x); a.y = fmaf(s, w.y, a.y);
    a.z = fmaf(s, w.z, a.z); a.w = fmaf(s, w.w, a.w); return a;
}

// Decode edge_index element `pos` for int64 or int32 buffers; clamp to range.
__device__ __forceinline__ int load_idx(const void* ei, int pos) {
    int v;
    if (g_is64) v = (int)((const long long*)ei)[pos];
    else        v = ((const int*)ei)[pos];
    return min(max(v, 0), NN - 1);
}

// ---------------- dtype probe ----------------------------------------------
__global__ void k_detect(const int* __restrict__ ei32) {
    __shared__ int s_any;
    if (threadIdx.x == 0) s_any = 0;
    __syncthreads();
    int any = 0;
    for (int i = threadIdx.x; i < 4096; i += blockDim.x) any |= ei32[2 * i + 1];
    if (any) atomicOr(&s_any, 1);
    __syncthreads();
    if (threadIdx.x == 0) g_is64 = (s_any == 0) ? 1 : 0;
}

// ---------------- CSR build -------------------------------------------------

__global__ void k_zero() {
    int idx = blockIdx.x * blockDim.x + threadIdx.x;
    if (idx <= NN) g_rowstart[idx] = 0;
    if (idx < NN)  g_cursor[idx]   = 0;
}

__global__ void k_count(const void* __restrict__ ei) {
    int e = blockIdx.x * blockDim.x + threadIdx.x;
    if (e >= NEDGE) return;
    int d = load_idx(ei, NEDGE + e);
    atomicAdd(&g_rowstart[d + 1], 1);
}

__global__ void k_scan1() {  // per-512-block inclusive scan
    __shared__ int sh[512];
    int tid = threadIdx.x;
    int idx = blockIdx.x * 512 + tid;
    int v = (idx <= NN) ? g_rowstart[idx] : 0;
    sh[tid] = v; __syncthreads();
    for (int off = 1; off < 512; off <<= 1) {
        int t = (tid >= off) ? sh[tid - off] : 0;
        __syncthreads();
        sh[tid] += t; __syncthreads();
    }
    if (idx <= NN) g_rowstart[idx] = sh[tid];
    if (tid == 511) g_bsums[blockIdx.x] = sh[511];
}

__global__ void k_scan2() {  // exclusive scan of 40 block sums
    __shared__ int sh[64];
    int tid = threadIdx.x;
    int v = (tid < 40) ? g_bsums[tid] : 0;
    sh[tid] = v; __syncthreads();
    for (int off = 1; off < 64; off <<= 1) {
        int t = (tid >= off) ? sh[tid - off] : 0;
        __syncthreads();
        sh[tid] += t; __syncthreads();
    }
    if (tid < 40) g_bsums[tid] = sh[tid] - v;
}

__global__ void k_scan3() {
    int idx = blockIdx.x * blockDim.x + threadIdx.x;
    if (idx <= NN) g_rowstart[idx] += g_bsums[idx >> 9];
}

__global__ void k_scatter(const void* __restrict__ ei) {
    int e = blockIdx.x * blockDim.x + threadIdx.x;
    if (e >= NEDGE) return;
    int s = load_idx(ei, e);
    int d = load_idx(ei, NEDGE + e);
    int pos = atomicAdd(&g_cursor[d], 1);
    int slot = g_rowstart[d] + pos;
    if (slot >= 0 && slot < NEDGE) g_csr[slot] = s;
}

// ---------------- aggregated input scalars: S = (I+A) x ---------------------
// Thread per (node, eig). x is 320KB -> L1/L2-resident gathers.

__global__ void k_sagg(const float* __restrict__ x) {
    int idx = blockIdx.x * blockDim.x + threadIdx.x;
    if (idx >= NN * 4) return;
    int i = idx >> 2, k = idx & 3;
    float s = x[i * 4 + k];
    int e0 = g_rowstart[i], e1 = g_rowstart[i + 1];
    for (int e = e0; e < e1; e++) s += __ldg(x + g_csr[e] * 4 + k);
    g_sx[idx] = s;
}

// ---------------- weight-product prep: 3 blocks, one product each -----------

__global__ void k_prep(const float* __restrict__ c0W2, const float* __restrict__ c0b2,
                       const float* __restrict__ c1W1,
                       const float* __restrict__ c1W2, const float* __restrict__ c1b2,
                       const float* __restrict__ c2W1,
                       const float* __restrict__ c2W2, const float* __restrict__ c2b2,
                       const float* __restrict__ rW1,  const float* __restrict__ rb1) {
    __shared__ __align__(16) float sA[4096], sB[4096], sb2[64];
    const float *W2, *b2, *W1, *addb; float scale; float *P, *v;
    if (blockIdx.x == 0)      { W2 = c0W2; b2 = c0b2; W1 = c1W1; scale = 1.f; addb = 0;   P = g_P1; v = g_v1; }
    else if (blockIdx.x == 1) { W2 = c1W2; b2 = c1b2; W1 = c2W1; scale = 1.f; addb = 0;   P = g_P2; v = g_v2; }
    else                      { W2 = c2W2; b2 = c2b2; W1 = rW1;  scale = 2.f; addb = rb1; P = g_Pr; v = g_br; }

    int tid = threadIdx.x;
    for (int t = tid; t < 4096; t += 256) { sA[t] = W2[t]; sB[t] = W1[t]; }
    if (tid < 64) sb2[tid] = b2[tid];
    __syncthreads();

    for (int t = tid; t < 4096; t += 256) {
        int a = t >> 6, c = t & 63;
        float s = 0.f;
#pragma unroll 8
        for (int b = 0; b < 64; b++) s = fmaf(sA[a * 64 + b], sB[b * 64 + c], s);
        P[t] = s;
    }
    if (tid < 64) {
        float s = 0.f;
#pragma unroll 8
        for (int b = 0; b < 64; b++) s = fmaf(sb2[b], sB[b * 64 + tid], s);
        v[tid] = scale * s + (addb ? addb[tid] : 0.f);
    }
}

// ---------------- boundary 0->1, fused in S-space ---------------------------
// Thread per row (node i, copy c). y0_j = relu(sgn*S_j*W1+b1)@W2+b2 with S
// the AGGREGATED scalar; recompute the relu part per edge from 4B loads of
// g_sx, then apply the folded P1 GEMV in the same kernel.
//   g  = relu(sgn*S_i*W1+b1) + sum_j relu(sgn*S_j*W1+b1)
//   y1 = relu(g @ P1 + (1+deg)*v1 + b1_1)

__global__ __launch_bounds__(128) void k_b01(
        const float* __restrict__ W1, const float* __restrict__ b1,
        const float* __restrict__ P1, const float* __restrict__ v1,
        const float* __restrict__ b11,
        float* __restrict__ out) {
    __shared__ __align__(16) float sW1[64], sb1[64], sP[4096], sv[64], sb[64];
    for (int t = threadIdx.x; t < 4096; t += 128) sP[t] = P1[t];
    if (threadIdx.x < 64) {
        sW1[threadIdx.x] = W1[threadIdx.x]; sb1[threadIdx.x] = b1[threadIdx.x];
        sv[threadIdx.x]  = v1[threadIdx.x]; sb[threadIdx.x]  = b11[threadIdx.x];
    }
    __syncthreads();

    int row = blockIdx.x * 128 + threadIdx.x;   // grid = R8/128 exactly
    int i = row >> 3, c = row & 7, k = c & 3;
    float sgn = (c >= 4) ? -1.0f : 1.0f;

    int e0 = g_rowstart[i], e1 = g_rowstart[i + 1];

    // g = relu(sgn*S_i*W1 + b1) + sum over neighbors (their aggregated S_j)
    float g[64];
    {
        float s = sgn * g_sx[i * 4 + k];
#pragma unroll
        for (int m = 0; m < 64; m++) g[m] = fmaxf(fmaf(s, sW1[m], sb1[m]), 0.0f);
    }
    for (int e = e0; e < e1; e++) {
        float s = sgn * g_sx[g_csr[e] * 4 + k];
#pragma unroll
        for (int m = 0; m < 64; m++) g[m] += fmaxf(fmaf(s, sW1[m], sb1[m]), 0.0f);
    }

    // y1 = relu(g @ P1 + (1+deg)*v1 + b1_1)
    float degp1 = (float)(e1 - e0 + 1);
    float4 a[16];
#pragma unroll
    for (int j = 0; j < 16; j++)
        a[j] = f4fma(degp1, ((const float4*)sv)[j], ((const float4*)sb)[j]);

#pragma unroll 4
    for (int kk = 0; kk < 64; kk++) {
        float gk = g[kk];
        const float4* w = (const float4*)(sP + kk * 64);
#pragma unroll
        for (int j = 0; j < 16; j++) a[j] = f4fma(gk, w[j], a[j]);
    }

    float4* o = (float4*)(out + (size_t)row * 64);
#pragma unroll
    for (int j = 0; j < 16; j++) {
        float4 r = a[j];
        r.x = fmaxf(r.x, 0.0f); r.y = fmaxf(r.y, 0.0f);
        r.z = fmaxf(r.z, 0.0f); r.w = fmaxf(r.w, 0.0f);
        o[j] = r;
    }
}

// ---------------- aggregation: warp per node, coalesced 2KB row gather ------

__global__ void k_agg(const float* __restrict__ h, float* __restrict__ z) {
    int gw   = (blockIdx.x * blockDim.x + threadIdx.x) >> 5;
    int lane = threadIdx.x & 31;
    if (gw >= NN) return;
    const float4* self = (const float4*)(h + (size_t)gw * ROWF);
    float4 a0 = self[lane], a1 = self[32 + lane], a2 = self[64 + lane], a3 = self[96 + lane];
    int e0 = g_rowstart[gw], e1 = g_rowstart[gw + 1];
    for (int e = e0; e < e1; e++) {
        const float4* src = (const float4*)(h + (size_t)g_csr[e] * ROWF);
        float4 v0 = src[lane], v1 = src[32 + lane], v2 = src[64 + lane], v3 = src[96 + lane];
        a0 = f4add(a0, v0); a1 = f4add(a1, v1); a2 = f4add(a2, v2); a3 = f4add(a3, v3);
    }
    float4* zo = (float4*)(z + (size_t)gw * ROWF);
    zo[lane] = a0; zo[32 + lane] = a1; zo[64 + lane] = a2; zo[96 + lane] = a3;
}

// ---------------- folded conv layer: y' = relu(g @ P + (1+deg)v + b1) -------

__global__ __launch_bounds__(128) void k_lin(
        const float* __restrict__ in,
        const float* __restrict__ P, const float* __restrict__ v,
        const float* __restrict__ b1,
        float* __restrict__ out) {
    __shared__ __align__(16) float sP[4096], sv[64], sb[64];
    for (int t = threadIdx.x; t < 4096; t += 128) sP[t] = P[t];
    if (threadIdx.x < 64) { sv[threadIdx.x] = v[threadIdx.x]; sb[threadIdx.x] = b1[threadIdx.x]; }
    __syncthreads();

    int row = blockIdx.x * 128 + threadIdx.x;   // grid = R8/128 exactly
    int node = row >> 3;
    float degp1 = (float)(g_rowstart[node + 1] - g_rowstart[node] + 1);

    float4 a[16];
#pragma unroll
    for (int j = 0; j < 16; j++)
        a[j] = f4fma(degp1, ((const float4*)sv)[j], ((const float4*)sb)[j]);

    const float4* ir = (const float4*)(in + (size_t)row * 64);
#pragma unroll 4
    for (int kk = 0; kk < 16; kk++) {
        float4 f = ir[kk];
        float zs[4] = {f.x, f.y, f.z, f.w};
#pragma unroll
        for (int u = 0; u < 4; u++) {
            float zk = zs[u];
            const float4* w = (const float4*)(sP + (kk * 4 + u) * 64);
#pragma unroll
            for (int j = 0; j < 16; j++) a[j] = f4fma(zk, w[j], a[j]);
        }
    }
    float4* o = (float4*)(out + (size_t)row * 64);
#pragma unroll
    for (int j = 0; j < 16; j++) {
        float4 r = a[j];
        r.x = fmaxf(r.x, 0.0f); r.y = fmaxf(r.y, 0.0f);
        r.z = fmaxf(r.z, 0.0f); r.w = fmaxf(r.w, 0.0f);
        o[j] = r;
    }
}

// ---------------- folded pool + rho: thread per node ------------------------

__global__ void k_rho(const float* __restrict__ y2,
                      const float* __restrict__ W2, const float* __restrict__ b2,
                      float* __restrict__ out) {
    __shared__ __align__(16) float sW1[4096], sW2[1024], sb1[64], sb2[16];
    for (int t = threadIdx.x; t < 4096; t += blockDim.x) sW1[t] = g_Pr[t];
    for (int t = threadIdx.x; t < 1024; t += blockDim.x) sW2[t] = W2[t];
    if (threadIdx.x < 64) sb1[threadIdx.x] = g_br[threadIdx.x];
    if (threadIdx.x < 16) sb2[threadIdx.x] = b2[threadIdx.x];
    __syncthreads();

    int n = blockIdx.x * blockDim.x + threadIdx.x;
    if (n >= NN) return;

    float p[64];
    {
        const float4* base = (const float4*)(y2 + (size_t)n * ROWF);
#pragma unroll
        for (int j = 0; j < 16; j++) {
            float4 s = base[j];
#pragma unroll
            for (int cc = 1; cc < 8; cc++) s = f4add(s, base[cc * 16 + j]);
            p[4 * j + 0] = s.x * 0.25f; p[4 * j + 1] = s.y * 0.25f;
            p[4 * j + 2] = s.z * 0.25f; p[4 * j + 3] = s.w * 0.25f;
        }
    }

    float4 acc[4];
#pragma unroll
    for (int j = 0; j < 4; j++) acc[j] = ((const float4*)sb2)[j];
#pragma unroll 4
    for (int m = 0; m < 64; m++) {
        float d = sb1[m];
#pragma unroll
        for (int k = 0; k < 64; k++) d = fmaf(p[k], sW1[k * 64 + m], d);
        d = fmaxf(d, 0.0f);
        const float4* wv = (const float4*)(sW2 + m * 16);
#pragma unroll
        for (int j = 0; j < 4; j++) acc[j] = f4fma(d, wv[j], acc[j]);
    }
    float4* o = (float4*)(out + (size_t)n * 16);
#pragma unroll
    for (int j = 0; j < 4; j++) o[j] = acc[j];
}

// ---------------------------------------------------------------------------

extern "C" void kernel_launch(void* const* d_in, const int* in_sizes, int n_in,
                              void* d_out, int out_size) {
    const float* x  = (const float*)d_in[0];
    const void*  ei = d_in[1];   // int32 or int64, probed on device
    const float* c0W1 = (const float*)d_in[2];
    const float* c0b1 = (const float*)d_in[3];
    const float* c0W2 = (const float*)d_in[4];
    const float* c0b2 = (const float*)d_in[5];
    const float* c1W1 = (const float*)d_in[6];
    const float* c1b1 = (const float*)d_in[7];
    const float* c1W2 = (const float*)d_in[8];
    const float* c1b2 = (const float*)d_in[9];
    const float* c2W1 = (const float*)d_in[10];
    const float* c2b1 = (const float*)d_in[11];
    const float* c2W2 = (const float*)d_in[12];
    const float* c2b2 = (const float*)d_in[13];
    const float* rW1  = (const float*)d_in[14];
    const float* rb1  = (const float*)d_in[15];
    const float* rW2  = (const float*)d_in[16];
    const float* rb2  = (const float*)d_in[17];
    float* out = (float*)d_out;

    float *A, *B, *P1, *V1, *P2, *V2;
    cudaGetSymbolAddress((void**)&A,  g_bufA);
    cudaGetSymbolAddress((void**)&B,  g_bufB);
    cudaGetSymbolAddress((void**)&P1, g_P1);
    cudaGetSymbolAddress((void**)&V1, g_v1);
    cudaGetSymbolAddress((void**)&P2, g_P2);
    cudaGetSymbolAddress((void**)&V2, g_v2);

    // dtype probe + CSR build + weight folding (per launch; capturable)
    k_detect<<<1, 256>>>((const int*)ei);
    k_zero<<<(NN + 256) / 256, 256>>>();
    k_count<<<NEDGE / 256, 256>>>(ei);
    k_scan1<<<40, 512>>>();
    k_scan2<<<1, 64>>>();
    k_scan3<<<(NN + 256) / 256, 256>>>();
    k_scatter<<<NEDGE / 256, 256>>>(ei);
    k_prep<<<3, 256>>>(c0W2, c0b2, c1W1, c1W2, c1b2, c2W1, c2W2, c2b2, rW1, rb1);

    // aggregated input scalars S = (I+A)x, then boundary 0->1 in S-space
    k_sagg<<<(NN * 4 + 255) / 256, 256>>>(x);
    k_b01<<<R8 / 128, 128>>>(c0W1, c0b1, P1, V1, c1b1, A);

    // boundary 1->2: agg y1, folded GEMV -> y2
    k_agg<<<NN / 8, 256>>>(A, B);
    k_lin<<<R8 / 128, 128>>>(B, P2, V2, c2b1, A);

    // folded pool + rho (W2_2 folded through pool into rho layer 1)
    k_rho<<<(NN + 255) / 256, 256>>>(A, rW2, rb2, out);
}